// round 12
// baseline (speedup 1.0000x reference)
#include <cuda_runtime.h>
#include <cuda_fp16.h>
#include <cstdint>

#define Bb 2
#define Ll 32768
#define Cc 128
#define NTOK 512
#define HD 32

// ---- smem byte offsets (per 128-thread CTA) ----
#define KF_OFF  0           // K fp16: 512 rows x 64B (swizzled)      32768
#define VH_OFF  32768       // V fp16 row-major: 512 rows x 80B       40960
                            //   (halves 32..39 = pad: d32=1.0 -> tensor row-sums)
#define OS_OFF  73728       // O fp32 [256][36] staging               36864
#define WS_OFF  110592      // weights [27][32] f32                    3456
#define BS_OFF  114048      // bias [32] f32                            128
#define SMEM_BYTES 114176   // x2 CTAs/SM

static __device__ __forceinline__ uint32_t s2u(const void* p){
    uint32_t a;
    asm("{ .reg .u64 t; cvta.to.shared.u64 t, %1; cvt.u32.u64 %0, t; }" : "=r"(a) : "l"(p));
    return a;
}
static __device__ __forceinline__ uint32_t pk2h(float a, float b){
    uint32_t r; asm("cvt.rn.f16x2.f32 %0, %1, %2;" : "=r"(r) : "f"(b), "f"(a)); return r;
}
static __device__ __forceinline__ uint32_t ex2h2(uint32_t a){
    uint32_t r; asm("ex2.approx.f16x2 %0, %1;" : "=r"(r) : "r"(a)); return r;
}
static __device__ __forceinline__ void ldm4(uint32_t* r, uint32_t a){
    asm volatile("ldmatrix.sync.aligned.m8n8.x4.shared.b16 {%0,%1,%2,%3}, [%4];"
        : "=r"(r[0]), "=r"(r[1]), "=r"(r[2]), "=r"(r[3]) : "r"(a));
}
static __device__ __forceinline__ void ldm4t(uint32_t* r, uint32_t a){
    asm volatile("ldmatrix.sync.aligned.m8n8.x4.trans.shared.b16 {%0,%1,%2,%3}, [%4];"
        : "=r"(r[0]), "=r"(r[1]), "=r"(r[2]), "=r"(r[3]) : "r"(a));
}
static __device__ __forceinline__ void ldm2t(uint32_t* r, uint32_t a){
    asm volatile("ldmatrix.sync.aligned.m8n8.x2.trans.shared.b16 {%0,%1}, [%2];"
        : "=r"(r[0]), "=r"(r[1]) : "r"(a));
}
static __device__ __forceinline__ void mma16816(float* d, const uint32_t* a, uint32_t b0, uint32_t b1){
    asm volatile("mma.sync.aligned.m16n8k16.row.col.f32.f16.f16.f32 "
        "{%0,%1,%2,%3},{%4,%5,%6,%7},{%8,%9},{%0,%1,%2,%3};"
        : "+f"(d[0]), "+f"(d[1]), "+f"(d[2]), "+f"(d[3])
        : "r"(a[0]), "r"(a[1]), "r"(a[2]), "r"(a[3]), "r"(b0), "r"(b1));
}
static __device__ __forceinline__ void sts_v4(uint32_t a, uint32_t x, uint32_t y, uint32_t z, uint32_t w){
    asm volatile("st.shared.v4.b32 [%0], {%1,%2,%3,%4};" :: "r"(a), "r"(x), "r"(y), "r"(z), "r"(w) : "memory");
}
static __device__ __forceinline__ void lds_v4(uint32_t* r, uint32_t a){
    asm volatile("ld.shared.v4.b32 {%0,%1,%2,%3}, [%4];"
        : "=r"(r[0]), "=r"(r[1]), "=r"(r[2]), "=r"(r[3]) : "r"(a));
}
// K row addressing: 64B rows; 16B-chunk c rotated by (row>>1) -> conflict-free ldmatrix
static __device__ __forceinline__ uint32_t kaddr(int n, int c){
    return (uint32_t)n*64u + ((((uint32_t)c + ((uint32_t)n >> 1)) & 3u) * 16u);
}

__global__ void __launch_bounds__(128, 2)
lepe_hmma(const float* __restrict__ qkv,
          const float* __restrict__ lw,
          const float* __restrict__ lb,
          float* __restrict__ out)
{
    extern __shared__ char sm[];
    const uint32_t smb = s2u(sm);
    const int tid = threadIdx.x;
    const int wid = tid >> 5, lane = tid & 31;

    const int bx = blockIdx.x;            // (window, head, qhalf)
    const int win = bx >> 3, head = (bx >> 1) & 3, qhalf = bx & 1;
    const int b  = win >> 6;
    const int tB = (win >> 4) & 3;
    const int wB = win & 15;
    const size_t batch_off = (size_t)b * Ll * Cc;
    const int chan  = head * HD;
    const int lbase = tB*8192 + wB*4;

    const float* qg = qkv + batch_off;
    const float* kg = qkv + (size_t)1*Bb*Ll*Cc + batch_off;
    const float* vg = qkv + (size_t)2*Bb*Ll*Cc + batch_off;

    // ---------- stage K fp16 (swizzled), V fp16 row-major (+ones pad) ----------
    {
        const int q = tid & 3;            // 4 threads per row, 8 d-values each
        const int rbase = tid >> 2;       // 0..31
        for (int it = 0; it < 16; it++){
            const int j = it*32 + rbase;
            const int t = j >> 8, h = (j >> 2) & 63, ws = j & 3;
            const size_t l = (size_t)(lbase + t*4096 + h*64 + ws);
            const float4 k0 = *(const float4*)(kg + l*Cc + chan + q*8);
            const float4 k1 = *(const float4*)(kg + l*Cc + chan + q*8 + 4);
            sts_v4(smb + KF_OFF + kaddr(j, q),
                   pk2h(k0.x, k0.y), pk2h(k0.z, k0.w),
                   pk2h(k1.x, k1.y), pk2h(k1.z, k1.w));

            const float4 v0 = *(const float4*)(vg + l*Cc + chan + q*8);
            const float4 v1 = *(const float4*)(vg + l*Cc + chan + q*8 + 4);
            sts_v4(smb + VH_OFF + (uint32_t)j*80u + (uint32_t)q*16u,
                   pk2h(v0.x, v0.y), pk2h(v0.z, v0.w),
                   pk2h(v1.x, v1.y), pk2h(v1.z, v1.w));
            if (q == 3)   // pad: d32 = 1.0 (tensor row-sum column), rest 0
                sts_v4(smb + VH_OFF + (uint32_t)j*80u + 64u, 0x00003C00u, 0u, 0u, 0u);
        }
        for (int idx = tid; idx < 27*32; idx += 128){
            const int tap = idx >> 5, d = idx & 31;
            ((float*)(sm + WS_OFF))[tap*32 + d] = lw[(chan + d)*27 + tap];
        }
        if (tid < 32) ((float*)(sm + BS_OFF))[tid] = lb[chan + tid];
    }

    // ---------- Q fragments from gmem (scaled into log2 domain, fp16) ----------
    const int qb  = qhalf*256 + wid*64;   // global q-row base for this warp (64 rows)
    const int qbl = wid*64;               // local (within-CTA) row base
    uint32_t qf[4][2][4];
    {
        const float sc = 0.17677669529663689f * 1.4426950408889634f;
        #pragma unroll
        for (int mt = 0; mt < 4; mt++){
            const int r0 = qb + mt*16 + (lane >> 2);
            const int r1 = r0 + 8;
            const int t0 = r0 >> 8, h0 = (r0 >> 2) & 63, w0 = r0 & 3;
            const int t1 = r1 >> 8, h1 = (r1 >> 2) & 63, w1 = r1 & 3;
            const float* p0 = qg + (size_t)(lbase + t0*4096 + h0*64 + w0)*Cc + chan;
            const float* p1 = qg + (size_t)(lbase + t1*4096 + h1*64 + w1)*Cc + chan;
            #pragma unroll
            for (int kt = 0; kt < 2; kt++){
                const int d0 = kt*16 + 2*(lane & 3);
                const float2 x0 = *(const float2*)(p0 + d0);
                const float2 x1 = *(const float2*)(p1 + d0);
                const float2 x2 = *(const float2*)(p0 + d0 + 8);
                const float2 x3 = *(const float2*)(p1 + d0 + 8);
                qf[mt][kt][0] = pk2h(x0.x*sc, x0.y*sc);
                qf[mt][kt][1] = pk2h(x1.x*sc, x1.y*sc);
                qf[mt][kt][2] = pk2h(x2.x*sc, x2.y*sc);
                qf[mt][kt][3] = pk2h(x3.x*sc, x3.y*sc);
            }
        }
    }
    __syncthreads();

    // ---------- mainloop: 32 subchunks of 16 keys, mt=4 per warp ----------
    float oAcc[4][4][4];
    #pragma unroll
    for (int a = 0; a < 4; a++)
        #pragma unroll
        for (int b2 = 0; b2 < 4; b2++)
            #pragma unroll
            for (int c = 0; c < 4; c++) oAcc[a][b2][c] = 0.f;
    float oSum[4][4];
    #pragma unroll
    for (int a = 0; a < 4; a++)
        #pragma unroll
        for (int c = 0; c < 4; c++) oSum[a][c] = 0.f;

    const int lg = lane >> 3, lr = lane & 7;
    // ones-column fragment is row-independent -> hoist out of the loop
    uint32_t vs2[2];
    ldm2t(vs2, smb + VH_OFF + (uint32_t)(lane & 15)*80u + 64u);

    #pragma unroll 1
    for (int cs = 0; cs < 32; cs++){
        const int j0 = cs * 16;
        // K fragments (B operand for QK)
        uint32_t kh[2][4];
        #pragma unroll
        for (int nt = 0; nt < 2; nt++)
            ldm4(kh[nt], smb + KF_OFF + kaddr(j0 + nt*8 + lr, lg));
        // V fragments via ldmatrix.trans from row-major fp16 V
        uint32_t vh[2][4];
        #pragma unroll
        for (int dg = 0; dg < 2; dg++){
            const uint32_t a = smb + VH_OFF
                + (uint32_t)(j0 + (lg & 1)*8 + lr)*80u
                + (uint32_t)dg*32u + (uint32_t)(lg >> 1)*16u;
            ldm4t(vh[dg], a);
        }
        // S = Q K^T (single fp16 term) — 16 independent MMAs
        float s[4][2][4];
        #pragma unroll
        for (int mt = 0; mt < 4; mt++)
            #pragma unroll
            for (int nt = 0; nt < 2; nt++){
                float* sd = s[mt][nt];
                sd[0]=sd[1]=sd[2]=sd[3]=0.f;
                mma16816(sd, qf[mt][0], kh[nt][0], kh[nt][1]);
                mma16816(sd, qf[mt][1], kh[nt][2], kh[nt][3]);
            }
        // softmax in f16x2 + PV + tensor row-sum
        #pragma unroll
        for (int mt = 0; mt < 4; mt++){
            uint32_t ah[4];
            ah[0] = ex2h2(pk2h(s[mt][0][0], s[mt][0][1]));
            ah[1] = ex2h2(pk2h(s[mt][0][2], s[mt][0][3]));
            ah[2] = ex2h2(pk2h(s[mt][1][0], s[mt][1][1]));
            ah[3] = ex2h2(pk2h(s[mt][1][2], s[mt][1][3]));
            #pragma unroll
            for (int ntd = 0; ntd < 4; ntd++){
                const int dg = ntd >> 1;
                mma16816(oAcc[mt][ntd], ah, vh[dg][(ntd&1)*2], vh[dg][(ntd&1)*2+1]);
            }
            mma16816(oSum[mt], ah, vs2[0], vs2[1]);   // col d32 = Sum(p)
        }
    }

    // ---------- denominators (col 32 lives on lanes lane&3==0), stage O ----------
    #pragma unroll
    for (int mt = 0; mt < 4; mt++){
        const float d0 = __shfl_sync(0xffffffffu, oSum[mt][0], lane & ~3);
        const float d1 = __shfl_sync(0xffffffffu, oSum[mt][2], lane & ~3);
        const float p0 = 1.f / d0;
        const float p1 = 1.f / d1;
        const int r0 = qbl + mt*16 + (lane >> 2);   // local row
        #pragma unroll
        for (int ntd = 0; ntd < 4; ntd++){
            const int cc = ntd*8 + 2*(lane & 3);
            float2 a, b2;
            a.x  = oAcc[mt][ntd][0] * p0;
            a.y  = oAcc[mt][ntd][1] * p0;
            b2.x = oAcc[mt][ntd][2] * p1;
            b2.y = oAcc[mt][ntd][3] * p1;
            *(float2*)(sm + OS_OFF + r0*144 + cc*4)      = a;
            *(float2*)(sm + OS_OFF + (r0+8)*144 + cc*4)  = b2;
        }
    }
    __syncthreads();

    // ---------- epilogue: LePE conv (fp16 V) + bias + store (two rows/thread) ----------
    {
        const float* Wsm = (const float*)(sm + WS_OFF);
        const float* Bsm = (const float*)(sm + BS_OFF);

        #pragma unroll
        for (int rr = 0; rr < 2; rr++){
            const int r = tid + rr*128;        // local row 0..255 ; global = qhalf*256 + r
            float o[32];
            #pragma unroll
            for (int k = 0; k < 8; k++){
                const float4 f = *(const float4*)(sm + OS_OFF + r*144 + k*16);
                o[4*k+0]=f.x; o[4*k+1]=f.y; o[4*k+2]=f.z; o[4*k+3]=f.w;
            }
            const int rh = (r >> 2) & 63, rws = r & 3;
            #pragma unroll
            for (int dt = -1; dt <= 1; dt++){
                const int tt = qhalf + dt;
                if ((unsigned)tt >= 2u) continue;
                #pragma unroll
                for (int dh = -1; dh <= 1; dh++){
                    const int hh = rh + dh;
                    if ((unsigned)hh >= 64u) continue;
                    #pragma unroll
                    for (int dw = -1; dw <= 1; dw++){
                        const int ww2 = rws + dw;
                        if ((unsigned)ww2 >= 4u) continue;
                        const int n2 = tt*256 + hh*4 + ww2;
                        const uint32_t a0 = smb + VH_OFF + (uint32_t)n2*80u;
                        uint32_t vp[8], vq[8];
                        lds_v4(vp,     a0);
                        lds_v4(vp + 4, a0 + 16u);
                        lds_v4(vq,     a0 + 32u);
                        lds_v4(vq + 4, a0 + 48u);
                        const float* wr = Wsm + ((dt+1)*9 + (dh+1)*3 + (dw+1))*32;
                        #pragma unroll
                        for (int i = 0; i < 8; i++){
                            const float2 x = __half22float2(*reinterpret_cast<const __half2*>(&vp[i]));
                            o[2*i]   += wr[2*i]   * x.x;
                            o[2*i+1] += wr[2*i+1] * x.y;
                        }
                        #pragma unroll
                        for (int i = 0; i < 8; i++){
                            const float2 x = __half22float2(*reinterpret_cast<const __half2*>(&vq[i]));
                            o[16+2*i]   += wr[16+2*i]   * x.x;
                            o[16+2*i+1] += wr[16+2*i+1] * x.y;
                        }
                    }
                }
            }
            const size_t l = (size_t)(lbase + qhalf*4096 + rh*64 + rws);
            float* op = out + batch_off + l*Cc + chan;
            #pragma unroll
            for (int k = 0; k < 8; k++){
                float4 r4;
                r4.x = o[4*k+0] + Bsm[4*k+0];
                r4.y = o[4*k+1] + Bsm[4*k+1];
                r4.z = o[4*k+2] + Bsm[4*k+2];
                r4.w = o[4*k+3] + Bsm[4*k+3];
                ((float4*)op)[k] = r4;
            }
        }
    }
}

extern "C" void kernel_launch(void* const* d_in, const int* in_sizes, int n_in,
                              void* d_out, int out_size)
{
    const float* qkv = (const float*)d_in[0];
    const float* lw  = (const float*)d_in[1];
    const float* lb  = (const float*)d_in[2];
    float* out       = (float*)d_out;

    cudaFuncSetAttribute(lepe_hmma, cudaFuncAttributeMaxDynamicSharedMemorySize, SMEM_BYTES);
    lepe_hmma<<<1024, 128, SMEM_BYTES>>>(qkv, lw, lb, out);
}

// round 13
// speedup vs baseline: 1.1918x; 1.1918x over previous
#include <cuda_runtime.h>
#include <cuda_fp16.h>
#include <cstdint>

#define Bb 2
#define Ll 32768
#define Cc 128
#define NTOK 512
#define HD 32

// ---- smem byte offsets (per 256-thread CTA) ----
#define KF_OFF  0           // K fp16: 512 rows x 64B (swizzled)      32768
#define VH_OFF  32768       // V fp16 row-major: 512 rows x 80B       40960
                            //   (halves 32..39 = pad: d32=1.0 -> tensor row-sums)
#define OS_OFF  73728       // O fp32 [256][36] staging               36864
#define WS_OFF  110592      // weights [27][32] f32                    3456
#define BS_OFF  114048      // bias [32] f32                            128
#define SMEM_BYTES 114176   // x2 CTAs/SM = 228352 <= 228KB

static __device__ __forceinline__ uint32_t s2u(const void* p){
    uint32_t a;
    asm("{ .reg .u64 t; cvta.to.shared.u64 t, %1; cvt.u32.u64 %0, t; }" : "=r"(a) : "l"(p));
    return a;
}
static __device__ __forceinline__ uint32_t pk2h(float a, float b){
    uint32_t r; asm("cvt.rn.f16x2.f32 %0, %1, %2;" : "=r"(r) : "f"(b), "f"(a)); return r;
}
static __device__ __forceinline__ uint32_t ex2h2(uint32_t a){
    uint32_t r; asm("ex2.approx.f16x2 %0, %1;" : "=r"(r) : "r"(a)); return r;
}
static __device__ __forceinline__ void ldm4(uint32_t* r, uint32_t a){
    asm volatile("ldmatrix.sync.aligned.m8n8.x4.shared.b16 {%0,%1,%2,%3}, [%4];"
        : "=r"(r[0]), "=r"(r[1]), "=r"(r[2]), "=r"(r[3]) : "r"(a));
}
static __device__ __forceinline__ void ldm4t(uint32_t* r, uint32_t a){
    asm volatile("ldmatrix.sync.aligned.m8n8.x4.trans.shared.b16 {%0,%1,%2,%3}, [%4];"
        : "=r"(r[0]), "=r"(r[1]), "=r"(r[2]), "=r"(r[3]) : "r"(a));
}
static __device__ __forceinline__ void ldm2t(uint32_t* r, uint32_t a){
    asm volatile("ldmatrix.sync.aligned.m8n8.x2.trans.shared.b16 {%0,%1}, [%2];"
        : "=r"(r[0]), "=r"(r[1]) : "r"(a));
}
static __device__ __forceinline__ void mma16816(float* d, const uint32_t* a, uint32_t b0, uint32_t b1){
    asm volatile("mma.sync.aligned.m16n8k16.row.col.f32.f16.f16.f32 "
        "{%0,%1,%2,%3},{%4,%5,%6,%7},{%8,%9},{%0,%1,%2,%3};"
        : "+f"(d[0]), "+f"(d[1]), "+f"(d[2]), "+f"(d[3])
        : "r"(a[0]), "r"(a[1]), "r"(a[2]), "r"(a[3]), "r"(b0), "r"(b1));
}
static __device__ __forceinline__ void sts_v4(uint32_t a, uint32_t x, uint32_t y, uint32_t z, uint32_t w){
    asm volatile("st.shared.v4.b32 [%0], {%1,%2,%3,%4};" :: "r"(a), "r"(x), "r"(y), "r"(z), "r"(w) : "memory");
}
static __device__ __forceinline__ void lds_v4(uint32_t* r, uint32_t a){
    asm volatile("ld.shared.v4.b32 {%0,%1,%2,%3}, [%4];"
        : "=r"(r[0]), "=r"(r[1]), "=r"(r[2]), "=r"(r[3]) : "r"(a));
}
// K row addressing: 64B rows; 16B-chunk c rotated by (row>>1) -> conflict-free ldmatrix
static __device__ __forceinline__ uint32_t kaddr(int n, int c){
    return (uint32_t)n*64u + ((((uint32_t)c + ((uint32_t)n >> 1)) & 3u) * 16u);
}

__global__ void __launch_bounds__(256, 2)
lepe_hmma(const float* __restrict__ qkv,
          const float* __restrict__ lw,
          const float* __restrict__ lb,
          float* __restrict__ out)
{
    extern __shared__ char sm[];
    const uint32_t smb = s2u(sm);
    const int tid = threadIdx.x;
    const int wid = tid >> 5, lane = tid & 31;

    const int bx = blockIdx.x;            // (window, head, qhalf)
    const int win = bx >> 3, head = (bx >> 1) & 3, qhalf = bx & 1;
    const int b  = win >> 6;
    const int tB = (win >> 4) & 3;
    const int wB = win & 15;
    const size_t batch_off = (size_t)b * Ll * Cc;
    const int chan  = head * HD;
    const int lbase = tB*8192 + wB*4;

    const float* qg = qkv + batch_off;
    const float* kg = qkv + (size_t)1*Bb*Ll*Cc + batch_off;
    const float* vg = qkv + (size_t)2*Bb*Ll*Cc + batch_off;

    // ---------- stage K fp16 (swizzled), V fp16 row-major (+ones pad) ----------
    {
        const int q = tid & 3;            // 4 threads per row, 8 d-values each
        const int rbase = tid >> 2;       // 0..63
        for (int it = 0; it < 8; it++){
            const int j = it*64 + rbase;
            const int t = j >> 8, h = (j >> 2) & 63, ws = j & 3;
            const size_t l = (size_t)(lbase + t*4096 + h*64 + ws);
            const float4 k0 = *(const float4*)(kg + l*Cc + chan + q*8);
            const float4 k1 = *(const float4*)(kg + l*Cc + chan + q*8 + 4);
            sts_v4(smb + KF_OFF + kaddr(j, q),
                   pk2h(k0.x, k0.y), pk2h(k0.z, k0.w),
                   pk2h(k1.x, k1.y), pk2h(k1.z, k1.w));

            const float4 v0 = *(const float4*)(vg + l*Cc + chan + q*8);
            const float4 v1 = *(const float4*)(vg + l*Cc + chan + q*8 + 4);
            sts_v4(smb + VH_OFF + (uint32_t)j*80u + (uint32_t)q*16u,
                   pk2h(v0.x, v0.y), pk2h(v0.z, v0.w),
                   pk2h(v1.x, v1.y), pk2h(v1.z, v1.w));
            if (q == 3)   // pad: d32 = 1.0 (tensor row-sum column), rest 0
                sts_v4(smb + VH_OFF + (uint32_t)j*80u + 64u, 0x00003C00u, 0u, 0u, 0u);
        }
        for (int idx = tid; idx < 27*32; idx += 256){
            const int tap = idx >> 5, d = idx & 31;
            ((float*)(sm + WS_OFF))[tap*32 + d] = lw[(chan + d)*27 + tap];
        }
        if (tid < 32) ((float*)(sm + BS_OFF))[tid] = lb[chan + tid];
    }

    // ---------- Q fragments from gmem (scaled into log2 domain, fp16) ----------
    const int qb  = qhalf*256 + wid*32;   // global q-row base for this warp
    const int qbl = wid*32;               // local (within-CTA) row base
    uint32_t qf[2][2][4];
    {
        const float sc = 0.17677669529663689f * 1.4426950408889634f;
        #pragma unroll
        for (int mt = 0; mt < 2; mt++){
            const int r0 = qb + mt*16 + (lane >> 2);
            const int r1 = r0 + 8;
            const int t0 = r0 >> 8, h0 = (r0 >> 2) & 63, w0 = r0 & 3;
            const int t1 = r1 >> 8, h1 = (r1 >> 2) & 63, w1 = r1 & 3;
            const float* p0 = qg + (size_t)(lbase + t0*4096 + h0*64 + w0)*Cc + chan;
            const float* p1 = qg + (size_t)(lbase + t1*4096 + h1*64 + w1)*Cc + chan;
            #pragma unroll
            for (int kt = 0; kt < 2; kt++){
                const int d0 = kt*16 + 2*(lane & 3);
                const float2 x0 = *(const float2*)(p0 + d0);
                const float2 x1 = *(const float2*)(p1 + d0);
                const float2 x2 = *(const float2*)(p0 + d0 + 8);
                const float2 x3 = *(const float2*)(p1 + d0 + 8);
                qf[mt][kt][0] = pk2h(x0.x*sc, x0.y*sc);
                qf[mt][kt][1] = pk2h(x1.x*sc, x1.y*sc);
                qf[mt][kt][2] = pk2h(x2.x*sc, x2.y*sc);
                qf[mt][kt][3] = pk2h(x3.x*sc, x3.y*sc);
            }
        }
    }
    __syncthreads();

    // ---------- mainloop: 32 subchunks of 16 keys ----------
    float oAcc[2][4][4];
    #pragma unroll
    for (int a = 0; a < 2; a++)
        #pragma unroll
        for (int b2 = 0; b2 < 4; b2++)
            #pragma unroll
            for (int c = 0; c < 4; c++) oAcc[a][b2][c] = 0.f;
    float oSum[2][4];
    #pragma unroll
    for (int a = 0; a < 2; a++)
        #pragma unroll
        for (int c = 0; c < 4; c++) oSum[a][c] = 0.f;

    const int lg = lane >> 3, lr = lane & 7;
    // ones-column fragment is row-independent -> hoisted
    uint32_t vs2[2];
    ldm2t(vs2, smb + VH_OFF + (uint32_t)(lane & 15)*80u + 64u);

    #pragma unroll 1
    for (int cs = 0; cs < 32; cs++){
        const int j0 = cs * 16;
        // K fragments (B operand for QK)
        uint32_t kh[2][4];
        #pragma unroll
        for (int nt = 0; nt < 2; nt++)
            ldm4(kh[nt], smb + KF_OFF + kaddr(j0 + nt*8 + lr, lg));
        // V fragments via ldmatrix.trans from row-major fp16 V
        uint32_t vh[2][4];
        #pragma unroll
        for (int dg = 0; dg < 2; dg++){
            const uint32_t a = smb + VH_OFF
                + (uint32_t)(j0 + (lg & 1)*8 + lr)*80u
                + (uint32_t)dg*32u + (uint32_t)(lg >> 1)*16u;
            ldm4t(vh[dg], a);
        }
        // S = Q K^T (single fp16 term)
        float s[2][2][4];
        #pragma unroll
        for (int mt = 0; mt < 2; mt++)
            #pragma unroll
            for (int nt = 0; nt < 2; nt++){
                float* sd = s[mt][nt];
                sd[0]=sd[1]=sd[2]=sd[3]=0.f;
                mma16816(sd, qf[mt][0], kh[nt][0], kh[nt][1]);
                mma16816(sd, qf[mt][1], kh[nt][2], kh[nt][3]);
            }
        // softmax in f16x2 + PV + tensor row-sum
        #pragma unroll
        for (int mt = 0; mt < 2; mt++){
            uint32_t ah[4];
            ah[0] = ex2h2(pk2h(s[mt][0][0], s[mt][0][1]));
            ah[1] = ex2h2(pk2h(s[mt][0][2], s[mt][0][3]));
            ah[2] = ex2h2(pk2h(s[mt][1][0], s[mt][1][1]));
            ah[3] = ex2h2(pk2h(s[mt][1][2], s[mt][1][3]));
            #pragma unroll
            for (int ntd = 0; ntd < 4; ntd++){
                const int dg = ntd >> 1;
                mma16816(oAcc[mt][ntd], ah, vh[dg][(ntd&1)*2], vh[dg][(ntd&1)*2+1]);
            }
            mma16816(oSum[mt], ah, vs2[0], vs2[1]);   // col d32 = Sum(p)
        }
    }

    // ---------- denominators (col 32 on lanes lane&3==0), stage O ----------
    #pragma unroll
    for (int mt = 0; mt < 2; mt++){
        const float d0 = __shfl_sync(0xffffffffu, oSum[mt][0], lane & ~3);
        const float d1 = __shfl_sync(0xffffffffu, oSum[mt][2], lane & ~3);
        const float p0 = 1.f / d0;
        const float p1 = 1.f / d1;
        const int r0 = qbl + mt*16 + (lane >> 2);   // local row
        #pragma unroll
        for (int ntd = 0; ntd < 4; ntd++){
            const int cc = ntd*8 + 2*(lane & 3);
            float2 a, b2;
            a.x  = oAcc[mt][ntd][0] * p0;
            a.y  = oAcc[mt][ntd][1] * p0;
            b2.x = oAcc[mt][ntd][2] * p1;
            b2.y = oAcc[mt][ntd][3] * p1;
            *(float2*)(sm + OS_OFF + r0*144 + cc*4)      = a;
            *(float2*)(sm + OS_OFF + (r0+8)*144 + cc*4)  = b2;
        }
    }
    __syncthreads();

    // ---------- epilogue: h-paired LePE conv + bias + store ----------
    // item = (h-pair g, w, chan-half c): rows rA=g*8+w (rh=2g), rB=g*8+4+w (rh=2g+1),
    // channels [16c,16c+16). Neighbor V segments shared between the two rows.
    {
        const int g = tid >> 3;            // 0..31
        const int w = (tid >> 1) & 3;
        const int c = tid & 1;
        const int c0 = c * 16;
        const int rA = g*8 + w;
        const int rB = g*8 + 4 + w;
        const float* Wsm = (const float*)(sm + WS_OFF);
        const float* Bsm = (const float*)(sm + BS_OFF);

        float oA[16], oB[16];
        #pragma unroll
        for (int k = 0; k < 4; k++){
            const float4 fA = *(const float4*)(sm + OS_OFF + rA*144 + c0*4 + k*16);
            const float4 fB = *(const float4*)(sm + OS_OFF + rB*144 + c0*4 + k*16);
            oA[4*k+0]=fA.x; oA[4*k+1]=fA.y; oA[4*k+2]=fA.z; oA[4*k+3]=fA.w;
            oB[4*k+0]=fB.x; oB[4*k+1]=fB.y; oB[4*k+2]=fB.z; oB[4*k+3]=fB.w;
        }

        #pragma unroll
        for (int tt = 0; tt < 2; tt++){
            const int dtp1 = tt - qhalf + 1;           // (dt+1) in 0..2
            const int wtT = dtp1 * 9;
            #pragma unroll
            for (int ho = -1; ho <= 2; ho++){          // hh = 2g + ho
                const int hh = 2*g + ho;
                if ((unsigned)hh >= 64u) continue;
                const int dhA = ho;                    // hh - 2g
                const int dhB = ho - 1;                // hh - (2g+1)
                #pragma unroll
                for (int dw = -1; dw <= 1; dw++){
                    const int ww2 = w + dw;
                    if ((unsigned)ww2 >= 4u) continue;
                    const int n2 = tt*256 + hh*4 + ww2;
                    uint32_t vp[8];
                    const uint32_t a0 = smb + VH_OFF + (uint32_t)n2*80u + (uint32_t)c0*2u;
                    lds_v4(vp,     a0);
                    lds_v4(vp + 4, a0 + 16u);
                    if (dhA <= 1){                     // valid tap for row A
                        const float* wr = Wsm + (wtT + (dhA+1)*3 + (dw+1))*32 + c0;
                        #pragma unroll
                        for (int i = 0; i < 8; i++){
                            const float2 x = __half22float2(*reinterpret_cast<const __half2*>(&vp[i]));
                            oA[2*i]   += wr[2*i]   * x.x;
                            oA[2*i+1] += wr[2*i+1] * x.y;
                        }
                    }
                    if (dhB >= -1){                    // valid tap for row B
                        const float* wr = Wsm + (wtT + (dhB+1)*3 + (dw+1))*32 + c0;
                        #pragma unroll
                        for (int i = 0; i < 8; i++){
                            const float2 x = __half22float2(*reinterpret_cast<const __half2*>(&vp[i]));
                            oB[2*i]   += wr[2*i]   * x.x;
                            oB[2*i+1] += wr[2*i+1] * x.y;
                        }
                    }
                }
            }
        }
        const int rhA = 2*g, rhB = 2*g + 1;
        const size_t lA = (size_t)(lbase + qhalf*4096 + rhA*64 + w);
        const size_t lB = (size_t)(lbase + qhalf*4096 + rhB*64 + w);
        float* opA = out + batch_off + lA*Cc + chan + c0;
        float* opB = out + batch_off + lB*Cc + chan + c0;
        #pragma unroll
        for (int k = 0; k < 4; k++){
            float4 r4;
            r4.x = oA[4*k+0] + Bsm[c0+4*k+0];
            r4.y = oA[4*k+1] + Bsm[c0+4*k+1];
            r4.z = oA[4*k+2] + Bsm[c0+4*k+2];
            r4.w = oA[4*k+3] + Bsm[c0+4*k+3];
            ((float4*)opA)[k] = r4;
            r4.x = oB[4*k+0] + Bsm[c0+4*k+0];
            r4.y = oB[4*k+1] + Bsm[c0+4*k+1];
            r4.z = oB[4*k+2] + Bsm[c0+4*k+2];
            r4.w = oB[4*k+3] + Bsm[c0+4*k+3];
            ((float4*)opB)[k] = r4;
        }
    }
}

extern "C" void kernel_launch(void* const* d_in, const int* in_sizes, int n_in,
                              void* d_out, int out_size)
{
    const float* qkv = (const float*)d_in[0];
    const float* lw  = (const float*)d_in[1];
    const float* lb  = (const float*)d_in[2];
    float* out       = (float*)d_out;

    cudaFuncSetAttribute(lepe_hmma, cudaFuncAttributeMaxDynamicSharedMemorySize, SMEM_BYTES);
    lepe_hmma<<<1024, 256, SMEM_BYTES>>>(qkv, lw, lb, out);
}

// round 14
// speedup vs baseline: 1.2035x; 1.0098x over previous
#include <cuda_runtime.h>
#include <cuda_fp16.h>
#include <cstdint>

#define Bb 2
#define Ll 32768
#define Cc 128
#define NTOK 512
#define HD 32

// ---- smem byte offsets (per 256-thread CTA) ----
#define KF_OFF  0           // K fp16: 512 rows x 64B (swizzled)      32768
#define VH_OFF  32768       // V fp16 row-major: 512 rows x 80B       40960
#define OS_OFF  73728       // O fp32 [256][36] staging (also Q fp16 stage pre-mainloop)
#define QS_OFF  OS_OFF      //   Q fp16: 256 rows x 64B (swizzled)    16384 (dead after fragment load)
#define WS_OFF  110592      // weights [27][32] f32                    3456
#define BS_OFF  114048      // bias [32] f32                            128
#define SMEM_BYTES 114176   // x2 CTAs/SM = 228352 <= 228KB

static __device__ __forceinline__ uint32_t s2u(const void* p){
    uint32_t a;
    asm("{ .reg .u64 t; cvta.to.shared.u64 t, %1; cvt.u32.u64 %0, t; }" : "=r"(a) : "l"(p));
    return a;
}
static __device__ __forceinline__ uint32_t pk2h(float a, float b){
    uint32_t r; asm("cvt.rn.f16x2.f32 %0, %1, %2;" : "=r"(r) : "f"(b), "f"(a)); return r;
}
static __device__ __forceinline__ uint32_t ex2h2(uint32_t a){
    uint32_t r; asm("ex2.approx.f16x2 %0, %1;" : "=r"(r) : "r"(a)); return r;
}
static __device__ __forceinline__ void ldm4(uint32_t* r, uint32_t a){
    asm volatile("ldmatrix.sync.aligned.m8n8.x4.shared.b16 {%0,%1,%2,%3}, [%4];"
        : "=r"(r[0]), "=r"(r[1]), "=r"(r[2]), "=r"(r[3]) : "r"(a));
}
static __device__ __forceinline__ void ldm4t(uint32_t* r, uint32_t a){
    asm volatile("ldmatrix.sync.aligned.m8n8.x4.trans.shared.b16 {%0,%1,%2,%3}, [%4];"
        : "=r"(r[0]), "=r"(r[1]), "=r"(r[2]), "=r"(r[3]) : "r"(a));
}
static __device__ __forceinline__ void mma16816(float* d, const uint32_t* a, uint32_t b0, uint32_t b1){
    asm volatile("mma.sync.aligned.m16n8k16.row.col.f32.f16.f16.f32 "
        "{%0,%1,%2,%3},{%4,%5,%6,%7},{%8,%9},{%0,%1,%2,%3};"
        : "+f"(d[0]), "+f"(d[1]), "+f"(d[2]), "+f"(d[3])
        : "r"(a[0]), "r"(a[1]), "r"(a[2]), "r"(a[3]), "r"(b0), "r"(b1));
}
static __device__ __forceinline__ void sts_v4(uint32_t a, uint32_t x, uint32_t y, uint32_t z, uint32_t w){
    asm volatile("st.shared.v4.b32 [%0], {%1,%2,%3,%4};" :: "r"(a), "r"(x), "r"(y), "r"(z), "r"(w) : "memory");
}
static __device__ __forceinline__ void lds_v4(uint32_t* r, uint32_t a){
    asm volatile("ld.shared.v4.b32 {%0,%1,%2,%3}, [%4];"
        : "=r"(r[0]), "=r"(r[1]), "=r"(r[2]), "=r"(r[3]) : "r"(a));
}
// 64B rows; 16B-chunk c rotated by (row>>1) -> conflict-free ldmatrix (used for K and Q)
static __device__ __forceinline__ uint32_t kaddr(int n, int c){
    return (uint32_t)n*64u + ((((uint32_t)c + ((uint32_t)n >> 1)) & 3u) * 16u);
}

__global__ void __launch_bounds__(256, 2)
lepe_hmma(const float* __restrict__ qkv,
          const float* __restrict__ lw,
          const float* __restrict__ lb,
          float* __restrict__ out)
{
    extern __shared__ char sm[];
    const uint32_t smb = s2u(sm);
    const int tid = threadIdx.x;
    const int wid = tid >> 5, lane = tid & 31;

    const int bx = blockIdx.x;            // (window, head, qhalf)
    const int win = bx >> 3, head = (bx >> 1) & 3, qhalf = bx & 1;
    const int b  = win >> 6;
    const int tB = (win >> 4) & 3;
    const int wB = win & 15;
    const size_t batch_off = (size_t)b * Ll * Cc;
    const int chan  = head * HD;
    const int lbase = tB*8192 + wB*4;

    const float* qg = qkv + batch_off;
    const float* kg = qkv + (size_t)1*Bb*Ll*Cc + batch_off;
    const float* vg = qkv + (size_t)2*Bb*Ll*Cc + batch_off;

    // ---------- stage K fp16 (swizzled), V fp16 row-major, Q fp16 (swizzled, scaled) ----------
    {
        const int q = tid & 3;            // 4 threads per row, 8 d-values each
        const int rbase = tid >> 2;       // 0..63
        for (int it = 0; it < 8; it++){
            const int j = it*64 + rbase;
            const int t = j >> 8, h = (j >> 2) & 63, ws = j & 3;
            const size_t l = (size_t)(lbase + t*4096 + h*64 + ws);
            const float4 k0 = *(const float4*)(kg + l*Cc + chan + q*8);
            const float4 k1 = *(const float4*)(kg + l*Cc + chan + q*8 + 4);
            sts_v4(smb + KF_OFF + kaddr(j, q),
                   pk2h(k0.x, k0.y), pk2h(k0.z, k0.w),
                   pk2h(k1.x, k1.y), pk2h(k1.z, k1.w));

            const float4 v0 = *(const float4*)(vg + l*Cc + chan + q*8);
            const float4 v1 = *(const float4*)(vg + l*Cc + chan + q*8 + 4);
            sts_v4(smb + VH_OFF + (uint32_t)j*80u + (uint32_t)q*16u,
                   pk2h(v0.x, v0.y), pk2h(v0.z, v0.w),
                   pk2h(v1.x, v1.y), pk2h(v1.z, v1.w));
        }
        // Q: 256 local rows (this qhalf), scaled into log2 domain
        const float sc = 0.17677669529663689f * 1.4426950408889634f;
        for (int it = 0; it < 4; it++){
            const int rl = it*64 + rbase;                 // local q-row 0..255
            const int r  = qhalf*256 + rl;                // global in-window row
            const int t = r >> 8, h = (r >> 2) & 63, ws = r & 3;
            const size_t l = (size_t)(lbase + t*4096 + h*64 + ws);
            const float4 q0 = *(const float4*)(qg + l*Cc + chan + q*8);
            const float4 q1 = *(const float4*)(qg + l*Cc + chan + q*8 + 4);
            sts_v4(smb + QS_OFF + kaddr(rl, q),
                   pk2h(q0.x*sc, q0.y*sc), pk2h(q0.z*sc, q0.w*sc),
                   pk2h(q1.x*sc, q1.y*sc), pk2h(q1.z*sc, q1.w*sc));
        }
        for (int idx = tid; idx < 27*32; idx += 256){
            const int tap = idx >> 5, d = idx & 31;
            ((float*)(sm + WS_OFF))[tap*32 + d] = lw[(chan + d)*27 + tap];
        }
        if (tid < 32) ((float*)(sm + BS_OFF))[tid] = lb[chan + tid];
    }
    __syncthreads();

    // ---------- Q fragments via ldmatrix from smem ----------
    const int qbl = wid*32;               // local (within-CTA) row base for this warp
    uint32_t qf[2][2][4];
    {
        const int row_off = (lane & 7) + ((lane >> 3) & 1)*8;
        const int ch_base = (lane >> 4);  // 0 or 1
        #pragma unroll
        for (int mt = 0; mt < 2; mt++)
            #pragma unroll
            for (int kt = 0; kt < 2; kt++)
                ldm4(qf[mt][kt], smb + QS_OFF + kaddr(qbl + mt*16 + row_off, ch_base + kt*2));
    }

    // ---------- mainloop: 32 subchunks of 16 keys ----------
    float oAcc[2][4][4];
    #pragma unroll
    for (int a = 0; a < 2; a++)
        #pragma unroll
        for (int b2 = 0; b2 < 4; b2++)
            #pragma unroll
            for (int c = 0; c < 4; c++) oAcc[a][b2][c] = 0.f;
    float oSum[2][4];
    #pragma unroll
    for (int a = 0; a < 2; a++)
        #pragma unroll
        for (int c = 0; c < 4; c++) oSum[a][c] = 0.f;

    const int lg = lane >> 3, lr = lane & 7;
    // ones B-fragment (B[k][0]=1, else 0) as compile-time constant
    const uint32_t vs2c = (lane < 4) ? 0x3C003C00u : 0u;

    #pragma unroll 1
    for (int cs = 0; cs < 32; cs++){
        const int j0 = cs * 16;
        // K fragments (B operand for QK)
        uint32_t kh[2][4];
        #pragma unroll
        for (int nt = 0; nt < 2; nt++)
            ldm4(kh[nt], smb + KF_OFF + kaddr(j0 + nt*8 + lr, lg));
        // V fragments via ldmatrix.trans from row-major fp16 V
        uint32_t vh[2][4];
        #pragma unroll
        for (int dg = 0; dg < 2; dg++){
            const uint32_t a = smb + VH_OFF
                + (uint32_t)(j0 + (lg & 1)*8 + lr)*80u
                + (uint32_t)dg*32u + (uint32_t)(lg >> 1)*16u;
            ldm4t(vh[dg], a);
        }
        // S = Q K^T (single fp16 term)
        float s[2][2][4];
        #pragma unroll
        for (int mt = 0; mt < 2; mt++)
            #pragma unroll
            for (int nt = 0; nt < 2; nt++){
                float* sd = s[mt][nt];
                sd[0]=sd[1]=sd[2]=sd[3]=0.f;
                mma16816(sd, qf[mt][0], kh[nt][0], kh[nt][1]);
                mma16816(sd, qf[mt][1], kh[nt][2], kh[nt][3]);
            }
        // softmax in f16x2 + PV + tensor row-sum
        #pragma unroll
        for (int mt = 0; mt < 2; mt++){
            uint32_t ah[4];
            ah[0] = ex2h2(pk2h(s[mt][0][0], s[mt][0][1]));
            ah[1] = ex2h2(pk2h(s[mt][0][2], s[mt][0][3]));
            ah[2] = ex2h2(pk2h(s[mt][1][0], s[mt][1][1]));
            ah[3] = ex2h2(pk2h(s[mt][1][2], s[mt][1][3]));
            #pragma unroll
            for (int ntd = 0; ntd < 4; ntd++){
                const int dg = ntd >> 1;
                mma16816(oAcc[mt][ntd], ah, vh[dg][(ntd&1)*2], vh[dg][(ntd&1)*2+1]);
            }
            mma16816(oSum[mt], ah, vs2c, vs2c);   // col n=0 = Sum(p)
        }
    }

    // ---------- denominators (col 0 on lanes lane&3==0), stage O ----------
    __syncthreads();   // QS region dead for everyone; OS may now be written
    #pragma unroll
    for (int mt = 0; mt < 2; mt++){
        const float d0 = __shfl_sync(0xffffffffu, oSum[mt][0], lane & ~3);
        const float d1 = __shfl_sync(0xffffffffu, oSum[mt][2], lane & ~3);
        const float p0 = 1.f / d0;
        const float p1 = 1.f / d1;
        const int r0 = qbl + mt*16 + (lane >> 2);   // local row
        #pragma unroll
        for (int ntd = 0; ntd < 4; ntd++){
            const int cc = ntd*8 + 2*(lane & 3);
            float2 a, b2;
            a.x  = oAcc[mt][ntd][0] * p0;
            a.y  = oAcc[mt][ntd][1] * p0;
            b2.x = oAcc[mt][ntd][2] * p1;
            b2.y = oAcc[mt][ntd][3] * p1;
            *(float2*)(sm + OS_OFF + r0*144 + cc*4)      = a;
            *(float2*)(sm + OS_OFF + (r0+8)*144 + cc*4)  = b2;
        }
    }
    __syncthreads();

    // ---------- epilogue: 2x2-paired LePE conv + bias + store ----------
    // item = (h-pair g, w-pair wp, chan-quad c): 4 output rows x 8 channels.
    // Each (tt,hh,ww) 16B V segment is loaded once and feeds up to 4 outputs.
    {
        const int g  = tid >> 3;           // 0..31
        const int wp = (tid >> 2) & 1;     // 0..1
        const int c  = tid & 3;            // 0..3
        const int c0 = c * 8;
        const float* Wsm = (const float*)(sm + WS_OFF);
        const float* Bsm = (const float*)(sm + BS_OFF);

        float o[2][2][8];
        #pragma unroll
        for (int a = 0; a < 2; a++)
            #pragma unroll
            for (int b2 = 0; b2 < 2; b2++){
                const int r = (2*g + a)*4 + 2*wp + b2;
                uint32_t t0[4], t1[4];
                lds_v4(t0, smb + OS_OFF + (uint32_t)r*144u + (uint32_t)c0*4u);
                lds_v4(t1, smb + OS_OFF + (uint32_t)r*144u + (uint32_t)c0*4u + 16u);
                #pragma unroll
                for (int i = 0; i < 4; i++){
                    o[a][b2][i]   = __uint_as_float(t0[i]);
                    o[a][b2][4+i] = __uint_as_float(t1[i]);
                }
            }

        #pragma unroll
        for (int tt = 0; tt < 2; tt++){
            const int wtT = (tt - qhalf + 1) * 9;      // (dt+1)*9
            #pragma unroll
            for (int ho = -1; ho <= 2; ho++){          // hh = 2g + ho
                const int hh = 2*g + ho;
                if ((unsigned)hh >= 64u) continue;
                #pragma unroll
                for (int wo = -1; wo <= 2; wo++){      // ww = 2wp + wo
                    const int ww = 2*wp + wo;
                    if ((unsigned)ww >= 4u) continue;
                    const int n2 = tt*256 + hh*4 + ww;
                    uint32_t vp[4];
                    lds_v4(vp, smb + VH_OFF + (uint32_t)n2*80u + (uint32_t)c0*2u);
                    float x[8];
                    #pragma unroll
                    for (int i = 0; i < 4; i++){
                        const float2 f = __half22float2(*reinterpret_cast<const __half2*>(&vp[i]));
                        x[2*i] = f.x; x[2*i+1] = f.y;
                    }
                    #pragma unroll
                    for (int a = 0; a < 2; a++){
                        const int dh = ho - a;
                        if (dh < -1 || dh > 1) continue;
                        #pragma unroll
                        for (int b2 = 0; b2 < 2; b2++){
                            const int dw = wo - b2;
                            if (dw < -1 || dw > 1) continue;
                            const float* wr = Wsm + (wtT + (dh+1)*3 + (dw+1))*32 + c0;
                            #pragma unroll
                            for (int i = 0; i < 8; i++)
                                o[a][b2][i] += wr[i] * x[i];
                        }
                    }
                }
            }
        }

        #pragma unroll
        for (int a = 0; a < 2; a++)
            #pragma unroll
            for (int b2 = 0; b2 < 2; b2++){
                const int rh = 2*g + a, rws = 2*wp + b2;
                const size_t l = (size_t)(lbase + qhalf*4096 + rh*64 + rws);
                float* op = out + batch_off + l*Cc + chan + c0;
                float4 r4;
                r4.x = o[a][b2][0] + Bsm[c0+0];
                r4.y = o[a][b2][1] + Bsm[c0+1];
                r4.z = o[a][b2][2] + Bsm[c0+2];
                r4.w = o[a][b2][3] + Bsm[c0+3];
                ((float4*)op)[0] = r4;
                r4.x = o[a][b2][4] + Bsm[c0+4];
                r4.y = o[a][b2][5] + Bsm[c0+5];
                r4.z = o[a][b2][6] + Bsm[c0+6];
                r4.w = o[a][b2][7] + Bsm[c0+7];
                ((float4*)op)[1] = r4;
            }
    }
}

extern "C" void kernel_launch(void* const* d_in, const int* in_sizes, int n_in,
                              void* d_out, int out_size)
{
    const float* qkv = (const float*)d_in[0];
    const float* lw  = (const float*)d_in[1];
    const float* lb  = (const float*)d_in[2];
    float* out       = (float*)d_out;

    cudaFuncSetAttribute(lepe_hmma, cudaFuncAttributeMaxDynamicSharedMemorySize, SMEM_BYTES);
    lepe_hmma<<<1024, 256, SMEM_BYTES>>>(qkv, lw, lb, out);
}